// round 13
// baseline (speedup 1.0000x reference)
#include <cuda_runtime.h>
#include <cuda_fp16.h>
#include <cstdint>

#define N_NODES 100000
#define N_EDGES 400000
#define HID 256
#define NT 54
#define XP 64            // x padded width (halves)
#define KW 320           // combined W width: 256 (W_hf) + 54 (W_if) + 10 pad
#define NCHUNK 5         // 5 x 64-k chunks
#define BM 128
#define BN 128
#define A_STG_B 32768    // 128 rows x 64 fp32 (chunk 4: 16KB fp16)
#define B_STG_B 16384    // 128 rows x 64 fp16
#define STG_BYTES (A_STG_B + B_STG_B)      // 49152
#define SMEM_DYN  (2 * STG_BYTES)          // 98304 -> 2 CTAs/SM
#define ZP 68            // z-tile pitch in half2

// device-global scratch (allocation-free)
__device__ __half g_x16[(size_t)N_NODES * XP];    // 12.8 MB, zero-padded x
__device__ __half g_Wc [(size_t)HID * KW];        // 160 KB  [W_hf | W_if | 0]

// ---------------------------------------------------------------------------
#define CP16(dst, src) \
    asm volatile("cp.async.cg.shared.global [%0], [%1], 16;" \
                 :: "r"(dst), "l"(src) : "memory")
#define CP_COMMIT()  asm volatile("cp.async.commit_group;" ::: "memory")
#define CP_WAIT1()   asm volatile("cp.async.wait_group 1;" ::: "memory")

__device__ __forceinline__ uint32_t smem_u32(const void* p) {
    uint32_t a;
    asm("{ .reg .u64 t; cvta.to.shared.u64 t, %1; cvt.u32.u64 %0, t; }"
        : "=r"(a) : "l"(p));
    return a;
}

__device__ __forceinline__ uint32_t packh2(float a, float b) {
    __half2 h = __floats2half2_rn(a, b);
    return *reinterpret_cast<uint32_t*>(&h);
}

__device__ __forceinline__ float fast_sigmoid(float z) {
    float t = 0.5f * z;
    asm("tanh.approx.f32 %0, %0;" : "+f"(t));
    return fmaf(0.5f, t, 0.5f);
}

// ---------------------------------------------------------------------------
// One prep kernel: zero out, pad x -> g_x16 (fp16), fuse W -> g_Wc (fp16).
// ---------------------------------------------------------------------------
__global__ void __launch_bounds__(256) prep(
    const float* __restrict__ x, const float* __restrict__ W_hf,
    const float* __restrict__ W_if, float4* __restrict__ out4)
{
    const size_t gs  = (size_t)gridDim.x * blockDim.x;
    const size_t gid = (size_t)blockIdx.x * blockDim.x + threadIdx.x;

    const size_t n_out = (size_t)N_NODES * HID / 4;
    const float4 z4 = make_float4(0.f, 0.f, 0.f, 0.f);
    for (size_t i = gid; i < n_out; i += gs) out4[i] = z4;

    const size_t n_x = (size_t)N_NODES * XP;
    for (size_t i = gid; i < n_x; i += gs) {
        size_t row = i >> 6;
        int c = (int)(i & 63);
        g_x16[i] = __float2half_rn(c < NT ? x[row * NT + c] : 0.0f);
    }

    const int n_w = HID * KW;
    for (int i = (int)gid; i < n_w; i += (int)gs) {
        int row = i / KW, c = i % KW;
        float v = 0.0f;
        if (c < HID)            v = W_hf[row * HID + c];
        else if (c < HID + NT)  v = W_if[row * NT + (c - HID)];
        g_Wc[i] = __float2half_rn(v);
    }
}

// ---------------------------------------------------------------------------
// Fused GEMM + epilogue (R11 schedule + fp16 x tail).
//   Chunks 0-3: A fp32 cp.async from h_all, fp16-packed in registers.
//   Chunk 4:    A fp16 cp.async from g_x16 (B-style layout, direct uint4).
//   B: fp16 cp.async from g_Wc.  K=320, BK=64, 2-stage.
//   Epilogue: z staged as half2, 4 cols/thread, tanh sigmoid, segment-sum.
// grid = (2, 3125); 256 thr = 8 warps 4(m)x2(n), warp tile 32x64. 2 CTAs/SM.
// ---------------------------------------------------------------------------
__global__ void __launch_bounds__(256, 2) fused_mma(
    const float* __restrict__ h_all, const float* __restrict__ c_all,
    const int*   __restrict__ seg,   const float* __restrict__ b_f,
    float* __restrict__ out)
{
    extern __shared__ float smf[];
    __shared__ int s_seg[BM];

    const int tid  = threadIdx.x;
    const int lane = tid & 31;
    const int warp = tid >> 5;
    const int wm = warp >> 1;          // 0..3
    const int wn = warp & 1;           // 0..1
    const int g  = lane >> 2, tg = lane & 3;
    const int n_off = blockIdx.x * BN;
    const size_t e0 = (size_t)blockIdx.y * BM;

    if (tid < BM) s_seg[tid] = seg[e0 + tid];
    __syncthreads();

    const uint32_t sbase = smem_u32(smf);

    // ---- hoisted loader bases ----
    const int a_r0 = tid >> 4;
    const int a_q  = tid & 15;
    const uint32_t a_dst = sbase + (uint32_t)a_r0 * 256
                         + (uint32_t)((a_q ^ (a_r0 & 1)) << 4);
    const float* a_src = h_all + (e0 + a_r0) * HID + a_q * 4;

    const int b_r0 = tid >> 3;
    const int b_q  = tid & 7;
    const uint32_t x_dst = sbase + (uint32_t)b_r0 * 128
                         + (uint32_t)((b_q ^ ((b_r0 & 1) << 2)) << 4);
    const uint32_t b_dst = x_dst + A_STG_B;
    const __half* b_src = g_Wc + (size_t)(n_off + b_r0) * KW + b_q * 8;

    auto load_chunk = [&](int kc, int stage) {
        const uint32_t so = (uint32_t)stage * STG_BYTES;
        #pragma unroll
        for (int t = 0; t < 4; ++t)                // B: 4 cp.async
            CP16(b_dst + so + (uint32_t)t * 4096u,
                 b_src + kc * 64 + t * 32 * KW);
        if (kc == 4) {
            #pragma unroll
            for (int t = 0; t < 4; ++t)            // A: x gather, fp16
                CP16(x_dst + so + (uint32_t)t * 4096u,
                     g_x16 + (size_t)s_seg[b_r0 + 32 * t] * XP + b_q * 8);
        } else {
            #pragma unroll
            for (int t = 0; t < 8; ++t)            // A: h stream, fp32
                CP16(a_dst + so + (uint32_t)t * 4096u,
                     a_src + kc * 64 + t * 16 * HID);
        }
    };

    load_chunk(0, 0); CP_COMMIT();
    load_chunk(1, 1); CP_COMMIT();

    float acc[2][8][4];
    #pragma unroll
    for (int i = 0; i < 2; ++i)
        #pragma unroll
        for (int j = 0; j < 8; ++j)
            #pragma unroll
            for (int q = 0; q < 4; ++q) acc[i][j][q] = 0.f;

    const int pr  = g & 1;             // A row parity for this thread
    const int psw = pr << 2;           // fp16 chunk swizzle

    #pragma unroll
    for (int kc = 0; kc < NCHUNK; ++kc) {
        CP_WAIT1();
        __syncthreads();

        const float*  Sa = smf + (kc & 1) * (STG_BYTES / 4);
        const __half* Sb = reinterpret_cast<const __half*>(Sa + BM * 64);

        #pragma unroll
        for (int wp = 0; wp < 2; ++wp) {
            const int p  = wp * 4 + tg;
            const int pc = p ^ psw;

            uint4 bv[8];
            #pragma unroll
            for (int j = 0; j < 8; ++j) {
                int cn = wn * 64 + j * 8 + g;
                bv[j] = *reinterpret_cast<const uint4*>(Sb + cn * 64 + pc * 8);
            }

            uint4 alo[2], ahi[2];
            if (kc == 4) {
                // x tail: A already fp16, B-style layout, direct load
                const __half* Sa16 = reinterpret_cast<const __half*>(Sa);
                #pragma unroll
                for (int i = 0; i < 2; ++i) {
                    int r0 = wm * 32 + i * 16 + g;
                    alo[i] = *reinterpret_cast<const uint4*>(Sa16 + r0 * 64 + pc * 8);
                    ahi[i] = *reinterpret_cast<const uint4*>(Sa16 + (r0 + 8) * 64 + pc * 8);
                }
            } else {
                const int cl = 2 * p + pr;
                const int ch = 2 * p + 1 - pr;
                #pragma unroll
                for (int i = 0; i < 2; ++i) {
                    int r0 = wm * 32 + i * 16 + g;
                    float4 La = *reinterpret_cast<const float4*>(Sa + r0 * 64 + cl * 4);
                    float4 Lb = *reinterpret_cast<const float4*>(Sa + r0 * 64 + ch * 4);
                    alo[i].x = packh2(La.x, La.y); alo[i].y = packh2(La.z, La.w);
                    alo[i].z = packh2(Lb.x, Lb.y); alo[i].w = packh2(Lb.z, Lb.w);
                    float4 Ha = *reinterpret_cast<const float4*>(Sa + (r0 + 8) * 64 + cl * 4);
                    float4 Hb = *reinterpret_cast<const float4*>(Sa + (r0 + 8) * 64 + ch * 4);
                    ahi[i].x = packh2(Ha.x, Ha.y); ahi[i].y = packh2(Ha.z, Ha.w);
                    ahi[i].z = packh2(Hb.x, Hb.y); ahi[i].w = packh2(Hb.z, Hb.w);
                }
            }
            #pragma unroll
            for (int s = 0; s < 2; ++s) {
                #pragma unroll
                for (int i = 0; i < 2; ++i) {
                    uint32_t a0 = s ? alo[i].z : alo[i].x;
                    uint32_t a1 = s ? ahi[i].z : ahi[i].x;
                    uint32_t a2 = s ? alo[i].w : alo[i].y;
                    uint32_t a3 = s ? ahi[i].w : ahi[i].y;
                    #pragma unroll
                    for (int j = 0; j < 8; ++j) {
                        uint32_t b0 = s ? bv[j].z : bv[j].x;
                        uint32_t b1 = s ? bv[j].w : bv[j].y;
                        asm volatile(
                            "mma.sync.aligned.m16n8k16.row.col.f32.f16.f16.f32 "
                            "{%0,%1,%2,%3},{%4,%5,%6,%7},{%8,%9},{%0,%1,%2,%3};"
                            : "+f"(acc[i][j][0]), "+f"(acc[i][j][1]),
                              "+f"(acc[i][j][2]), "+f"(acc[i][j][3])
                            : "r"(a0), "r"(a1), "r"(a2), "r"(a3),
                              "r"(b0), "r"(b1));
                    }
                }
            }
        }

        __syncthreads();
        if (kc + 2 < NCHUNK) load_chunk(kc + 2, kc & 1);
        CP_COMMIT();
    }

    // ---- epilogue: prefetch c_all first (hide DRAM latency behind STS) ----
    const int cg    = tid & 31;
    const int col0l = cg * 4;
    const int col0  = n_off + col0l;
    const int ebase = (tid >> 5) * 16;

    float4 cv[8];
    #pragma unroll
    for (int u = 0; u < 8; ++u)
        cv[u] = *reinterpret_cast<const float4*>(
            c_all + (e0 + ebase + u) * HID + col0);

    // ---- stage z tile as half2 [128][ZP], bank-conflict-free ----
    __half2* Sm2 = reinterpret_cast<__half2*>(smf);
    #pragma unroll
    for (int i = 0; i < 2; ++i)
        #pragma unroll
        for (int j = 0; j < 8; ++j) {
            int row = wm * 32 + i * 16 + g;
            int c2  = wn * 32 + j * 4 + tg;
            Sm2[row * ZP + c2]       = __floats2half2_rn(acc[i][j][0], acc[i][j][1]);
            Sm2[(row + 8) * ZP + c2] = __floats2half2_rn(acc[i][j][2], acc[i][j][3]);
        }
    __syncthreads();

    const float4 bf = *reinterpret_cast<const float4*>(b_f + col0);

    int prev = -1;
    float a0 = 0.f, a1 = 0.f, a2 = 0.f, a3 = 0.f;
    #pragma unroll
    for (int half = 0; half < 2; ++half) {
        float4 nx[8];
        if (half == 0) {
            #pragma unroll
            for (int u = 0; u < 8; ++u)
                nx[u] = *reinterpret_cast<const float4*>(
                    c_all + (e0 + ebase + 8 + u) * HID + col0);
        }
        #pragma unroll
        for (int u = 0; u < 8; ++u) {
            int e = ebase + half * 8 + u;
            float2 zlo = __half22float2(Sm2[e * ZP + cg * 2]);
            float2 zhi = __half22float2(Sm2[e * ZP + cg * 2 + 1]);
            float f0 = cv[u].x * fast_sigmoid(zlo.x + bf.x);
            float f1 = cv[u].y * fast_sigmoid(zlo.y + bf.y);
            float f2 = cv[u].z * fast_sigmoid(zhi.x + bf.z);
            float f3 = cv[u].w * fast_sigmoid(zhi.y + bf.w);
            int node = s_seg[e];
            if (node != prev) {
                if (prev >= 0) {
                    float* o = out + (size_t)prev * HID + col0;
                    atomicAdd(o,     a0); atomicAdd(o + 1, a1);
                    atomicAdd(o + 2, a2); atomicAdd(o + 3, a3);
                }
                prev = node;
                a0 = a1 = a2 = a3 = 0.f;
            }
            a0 += f0; a1 += f1; a2 += f2; a3 += f3;
        }
        if (half == 0) {
            #pragma unroll
            for (int u = 0; u < 8; ++u) cv[u] = nx[u];
        }
    }
    {
        float* o = out + (size_t)prev * HID + col0;
        atomicAdd(o,     a0); atomicAdd(o + 1, a1);
        atomicAdd(o + 2, a2); atomicAdd(o + 3, a3);
    }
}

// ---------------------------------------------------------------------------
extern "C" void kernel_launch(void* const* d_in, const int* in_sizes, int n_in,
                              void* d_out, int out_size)
{
    const float* x     = (const float*)d_in[0];
    const float* h_all = (const float*)d_in[1];
    const float* c_all = (const float*)d_in[2];
    const int*   seg   = (const int*)  d_in[3];
    const float* W_if  = (const float*)d_in[4];
    const float* W_hf  = (const float*)d_in[5];
    const float* b_f   = (const float*)d_in[6];
    float* out = (float*)d_out;

    cudaFuncSetAttribute(fused_mma,
        cudaFuncAttributeMaxDynamicSharedMemorySize, SMEM_DYN);

    prep<<<2048, 256>>>(x, W_hf, W_if, (float4*)out);
    dim3 grid(HID / BN, N_EDGES / BM);   // N-half fastest -> L2 A reuse
    fused_mma<<<grid, 256, SMEM_DYN>>>(h_all, c_all, seg, b_f, out);
}

// round 14
// speedup vs baseline: 1.0525x; 1.0525x over previous
#include <cuda_runtime.h>
#include <cuda_fp16.h>
#include <cstdint>

#define N_NODES 100000
#define N_EDGES 400000
#define HID 256
#define NT 54
#define XP 64            // x padded width (floats)
#define KW 320           // combined W width: 256 (W_hf) + 54 (W_if) + 10 pad
#define NCHUNK 5         // 5 x 64-k chunks
#define BM 128
#define BN 128
#define A_STG_B 32768    // 128 rows x 64 fp32
#define B_STG_B 16384    // 128 rows x 64 fp16
#define STG_BYTES (A_STG_B + B_STG_B)      // 49152
#define SMEM_DYN  (2 * STG_BYTES)          // 98304 -> 2 CTAs/SM
#define ZP 68            // z-tile pitch in half2

// device-global scratch (allocation-free)
__device__ float  g_x32[(size_t)N_NODES * XP];    // 25.6 MB, zero-padded x
__device__ __half g_Wc [(size_t)HID * KW];        // 160 KB  [W_hf | W_if | 0]

// ---------------------------------------------------------------------------
#define CP16(dst, src) \
    asm volatile("cp.async.cg.shared.global [%0], [%1], 16;" \
                 :: "r"(dst), "l"(src) : "memory")
#define CP_COMMIT()  asm volatile("cp.async.commit_group;" ::: "memory")
#define CP_WAIT1()   asm volatile("cp.async.wait_group 1;" ::: "memory")

__device__ __forceinline__ uint32_t smem_u32(const void* p) {
    uint32_t a;
    asm("{ .reg .u64 t; cvta.to.shared.u64 t, %1; cvt.u32.u64 %0, t; }"
        : "=r"(a) : "l"(p));
    return a;
}

__device__ __forceinline__ uint32_t packh2(float a, float b) {
    __half2 h = __floats2half2_rn(a, b);
    return *reinterpret_cast<uint32_t*>(&h);
}

__device__ __forceinline__ float fast_sigmoid(float z) {
    float t = 0.5f * z;
    asm("tanh.approx.f32 %0, %0;" : "+f"(t));
    return fmaf(0.5f, t, 0.5f);
}

// ---------------------------------------------------------------------------
// One prep kernel: zero out, pad x -> g_x32, fuse W -> g_Wc (fp16).
// ---------------------------------------------------------------------------
__global__ void __launch_bounds__(256) prep(
    const float* __restrict__ x, const float* __restrict__ W_hf,
    const float* __restrict__ W_if, float4* __restrict__ out4)
{
    const size_t gs  = (size_t)gridDim.x * blockDim.x;
    const size_t gid = (size_t)blockIdx.x * blockDim.x + threadIdx.x;

    const size_t n_out = (size_t)N_NODES * HID / 4;
    const float4 z4 = make_float4(0.f, 0.f, 0.f, 0.f);
    for (size_t i = gid; i < n_out; i += gs) out4[i] = z4;

    const size_t n_x = (size_t)N_NODES * XP;
    for (size_t i = gid; i < n_x; i += gs) {
        size_t row = i >> 6;
        int c = (int)(i & 63);
        g_x32[i] = (c < NT) ? x[row * NT + c] : 0.0f;
    }

    const int n_w = HID * KW;
    for (int i = (int)gid; i < n_w; i += (int)gs) {
        int row = i / KW, c = i % KW;
        float v = 0.0f;
        if (c < HID)            v = W_hf[row * HID + c];
        else if (c < HID + NT)  v = W_if[row * NT + (c - HID)];
        g_Wc[i] = __float2half_rn(v);
    }
}

// ---------------------------------------------------------------------------
// Fused GEMM + epilogue (R11 mainloop, frozen; epilogue with interior STG).
//   A: fp32 via cp.async from h_all / g_x32, fp16-converted in registers.
//   B: fp16 via cp.async from g_Wc.  K=320, BK=64, 2-stage.
//   Epilogue: z staged as half2, 4 cols/thread, tanh sigmoid, run-length
//   segment-sum; interior node runs flushed with STG.128, boundary runs
//   (first-in-range + final) with atomicAdd.
// grid = (2, 3125); 256 thr = 8 warps 4(m)x2(n), warp tile 32x64. 2 CTAs/SM.
// ---------------------------------------------------------------------------
__global__ void __launch_bounds__(256, 2) fused_mma(
    const float* __restrict__ h_all, const float* __restrict__ c_all,
    const int*   __restrict__ seg,   const float* __restrict__ b_f,
    float* __restrict__ out)
{
    extern __shared__ float smf[];
    __shared__ int s_seg[BM];

    const int tid  = threadIdx.x;
    const int lane = tid & 31;
    const int warp = tid >> 5;
    const int wm = warp >> 1;          // 0..3
    const int wn = warp & 1;           // 0..1
    const int g  = lane >> 2, tg = lane & 3;
    const int n_off = blockIdx.x * BN;
    const size_t e0 = (size_t)blockIdx.y * BM;

    if (tid < BM) s_seg[tid] = seg[e0 + tid];
    __syncthreads();

    const uint32_t sbase = smem_u32(smf);

    // ---- hoisted loader bases ----
    const int a_r0 = tid >> 4;
    const int a_q  = tid & 15;
    const uint32_t a_dst = sbase + (uint32_t)a_r0 * 256
                         + (uint32_t)((a_q ^ (a_r0 & 1)) << 4);
    const float* a_src = h_all + (e0 + a_r0) * HID + a_q * 4;

    const int b_r0 = tid >> 3;
    const int b_q  = tid & 7;
    const uint32_t b_dst = sbase + A_STG_B + (uint32_t)b_r0 * 128
                         + (uint32_t)((b_q ^ ((b_r0 & 1) << 2)) << 4);
    const __half* b_src = g_Wc + (size_t)(n_off + b_r0) * KW + b_q * 8;

    auto load_chunk = [&](int kc, int stage) {
        const uint32_t so = (uint32_t)stage * STG_BYTES;
        #pragma unroll
        for (int t = 0; t < 4; ++t)                // B: 4 cp.async
            CP16(b_dst + so + (uint32_t)t * 4096u,
                 b_src + kc * 64 + t * 32 * KW);
        if (kc == 4) {
            #pragma unroll
            for (int t = 0; t < 8; ++t)            // A: x gather (fp32)
                CP16(a_dst + so + (uint32_t)t * 4096u,
                     g_x32 + (size_t)s_seg[a_r0 + 16 * t] * XP + a_q * 4);
        } else {
            #pragma unroll
            for (int t = 0; t < 8; ++t)            // A: h stream (fp32)
                CP16(a_dst + so + (uint32_t)t * 4096u,
                     a_src + kc * 64 + t * 16 * HID);
        }
    };

    load_chunk(0, 0); CP_COMMIT();
    load_chunk(1, 1); CP_COMMIT();

    float acc[2][8][4];
    #pragma unroll
    for (int i = 0; i < 2; ++i)
        #pragma unroll
        for (int j = 0; j < 8; ++j)
            #pragma unroll
            for (int q = 0; q < 4; ++q) acc[i][j][q] = 0.f;

    const int pr  = g & 1;             // A row parity for this thread
    const int psw = pr << 2;           // fp16 chunk swizzle

    #pragma unroll
    for (int kc = 0; kc < NCHUNK; ++kc) {
        CP_WAIT1();
        __syncthreads();

        const float*  Sa = smf + (kc & 1) * (STG_BYTES / 4);
        const __half* Sb = reinterpret_cast<const __half*>(Sa + BM * 64);

        #pragma unroll
        for (int wp = 0; wp < 2; ++wp) {
            const int p  = wp * 4 + tg;
            const int cl = 2 * p + pr;
            const int ch = 2 * p + 1 - pr;
            const int pc = p ^ psw;

            uint4 bv[8];
            #pragma unroll
            for (int j = 0; j < 8; ++j) {
                int cn = wn * 64 + j * 8 + g;
                bv[j] = *reinterpret_cast<const uint4*>(Sb + cn * 64 + pc * 8);
            }

            uint4 alo[2], ahi[2];
            #pragma unroll
            for (int i = 0; i < 2; ++i) {
                int r0 = wm * 32 + i * 16 + g;
                float4 La = *reinterpret_cast<const float4*>(Sa + r0 * 64 + cl * 4);
                float4 Lb = *reinterpret_cast<const float4*>(Sa + r0 * 64 + ch * 4);
                alo[i].x = packh2(La.x, La.y); alo[i].y = packh2(La.z, La.w);
                alo[i].z = packh2(Lb.x, Lb.y); alo[i].w = packh2(Lb.z, Lb.w);
                float4 Ha = *reinterpret_cast<const float4*>(Sa + (r0 + 8) * 64 + cl * 4);
                float4 Hb = *reinterpret_cast<const float4*>(Sa + (r0 + 8) * 64 + ch * 4);
                ahi[i].x = packh2(Ha.x, Ha.y); ahi[i].y = packh2(Ha.z, Ha.w);
                ahi[i].z = packh2(Hb.x, Hb.y); ahi[i].w = packh2(Hb.z, Hb.w);
            }
            #pragma unroll
            for (int s = 0; s < 2; ++s) {
                #pragma unroll
                for (int i = 0; i < 2; ++i) {
                    uint32_t a0 = s ? alo[i].z : alo[i].x;
                    uint32_t a1 = s ? ahi[i].z : ahi[i].x;
                    uint32_t a2 = s ? alo[i].w : alo[i].y;
                    uint32_t a3 = s ? ahi[i].w : ahi[i].y;
                    #pragma unroll
                    for (int j = 0; j < 8; ++j) {
                        uint32_t b0 = s ? bv[j].z : bv[j].x;
                        uint32_t b1 = s ? bv[j].w : bv[j].y;
                        asm volatile(
                            "mma.sync.aligned.m16n8k16.row.col.f32.f16.f16.f32 "
                            "{%0,%1,%2,%3},{%4,%5,%6,%7},{%8,%9},{%0,%1,%2,%3};"
                            : "+f"(acc[i][j][0]), "+f"(acc[i][j][1]),
                              "+f"(acc[i][j][2]), "+f"(acc[i][j][3])
                            : "r"(a0), "r"(a1), "r"(a2), "r"(a3),
                              "r"(b0), "r"(b1));
                    }
                }
            }
        }

        __syncthreads();
        if (kc + 2 < NCHUNK) load_chunk(kc + 2, kc & 1);
        CP_COMMIT();
    }

    // ---- epilogue: prefetch c_all first (hide DRAM latency behind STS) ----
    const int cg    = tid & 31;
    const int col0l = cg * 4;
    const int col0  = n_off + col0l;
    const int ebase = (tid >> 5) * 16;

    float4 cv[8];
    #pragma unroll
    for (int u = 0; u < 8; ++u)
        cv[u] = *reinterpret_cast<const float4*>(
            c_all + (e0 + ebase + u) * HID + col0);

    // ---- stage z tile as half2 [128][ZP], bank-conflict-free ----
    __half2* Sm2 = reinterpret_cast<__half2*>(smf);
    #pragma unroll
    for (int i = 0; i < 2; ++i)
        #pragma unroll
        for (int j = 0; j < 8; ++j) {
            int row = wm * 32 + i * 16 + g;
            int c2  = wn * 32 + j * 4 + tg;
            Sm2[row * ZP + c2]       = __floats2half2_rn(acc[i][j][0], acc[i][j][1]);
            Sm2[(row + 8) * ZP + c2] = __floats2half2_rn(acc[i][j][2], acc[i][j][3]);
        }
    __syncthreads();

    const float4 bf = *reinterpret_cast<const float4*>(b_f + col0);
    const int first_node = s_seg[ebase];

    int prev = -1;
    float a0 = 0.f, a1 = 0.f, a2 = 0.f, a3 = 0.f;
    #pragma unroll
    for (int half = 0; half < 2; ++half) {
        float4 nx[8];
        if (half == 0) {
            #pragma unroll
            for (int u = 0; u < 8; ++u)
                nx[u] = *reinterpret_cast<const float4*>(
                    c_all + (e0 + ebase + 8 + u) * HID + col0);
        }
        #pragma unroll
        for (int u = 0; u < 8; ++u) {
            int e = ebase + half * 8 + u;
            float2 zlo = __half22float2(Sm2[e * ZP + cg * 2]);
            float2 zhi = __half22float2(Sm2[e * ZP + cg * 2 + 1]);
            float f0 = cv[u].x * fast_sigmoid(zlo.x + bf.x);
            float f1 = cv[u].y * fast_sigmoid(zlo.y + bf.y);
            float f2 = cv[u].z * fast_sigmoid(zhi.x + bf.z);
            float f3 = cv[u].w * fast_sigmoid(zhi.y + bf.w);
            int node = s_seg[e];
            if (node != prev) {
                if (prev >= 0) {
                    float* o = out + (size_t)prev * HID + col0;
                    if (prev == first_node) {      // may span range boundary
                        atomicAdd(o,     a0); atomicAdd(o + 1, a1);
                        atomicAdd(o + 2, a2); atomicAdd(o + 3, a3);
                    } else {                        // interior: exclusive
                        *reinterpret_cast<float4*>(o) =
                            make_float4(a0, a1, a2, a3);
                    }
                }
                prev = node;
                a0 = a1 = a2 = a3 = 0.f;
            }
            a0 += f0; a1 += f1; a2 += f2; a3 += f3;
        }
        if (half == 0) {
            #pragma unroll
            for (int u = 0; u < 8; ++u) cv[u] = nx[u];
        }
    }
    {   // final run may continue into the next range/tile: atomic
        float* o = out + (size_t)prev * HID + col0;
        atomicAdd(o,     a0); atomicAdd(o + 1, a1);
        atomicAdd(o + 2, a2); atomicAdd(o + 3, a3);
    }
}

// ---------------------------------------------------------------------------
extern "C" void kernel_launch(void* const* d_in, const int* in_sizes, int n_in,
                              void* d_out, int out_size)
{
    const float* x     = (const float*)d_in[0];
    const float* h_all = (const float*)d_in[1];
    const float* c_all = (const float*)d_in[2];
    const int*   seg   = (const int*)  d_in[3];
    const float* W_if  = (const float*)d_in[4];
    const float* W_hf  = (const float*)d_in[5];
    const float* b_f   = (const float*)d_in[6];
    float* out = (float*)d_out;

    cudaFuncSetAttribute(fused_mma,
        cudaFuncAttributeMaxDynamicSharedMemorySize, SMEM_DYN);

    prep<<<2048, 256>>>(x, W_hf, W_if, (float4*)out);
    dim3 grid(HID / BN, N_EDGES / BM);   // N-half fastest -> L2 A reuse
    fused_mma<<<grid, 256, SMEM_DYN>>>(h_all, c_all, seg, b_f, out);
}